// round 6
// baseline (speedup 1.0000x reference)
#include <cuda_runtime.h>
#include <cstdint>

// out[m][d] = sum_k x[m][k] * W[k][d];  M=8192, K=4096, N=32, fp32.
//
// bf16x3 split GEMM on mma.sync (tcgen05 rejected by harness sm_103 target).
//   D += Ahi*Bhi + Ahi*Blo + Alo*Bhi  (fp32 accum), rel_err ~5e-6.
//
// R5 vs R4 (45.1us, gemm: DRAM 41% / L1 53% / tensor 24% / occ 20% -> latency
// bound on half-filled L1 lines):
//  - A staged via cp.async into double-buffered smem (full 128B lines, 4
//    wf/instr, latency hidden by pipeline not warps); fragments via LDS.128
//    with parity swizzle (conflict-free).
//  - B table reordered [step][c][h][r] so every B LDG.128 covers 4 full lines.
//  - KSPLIT=8 -> 512 CTAs, single wave; fused deterministic reduce kept.

#define M_TOTAL 8192
#define K_TOTAL 4096
#define N_OUT   32
#define KSPLIT  8
#define KPER    (K_TOTAL / KSPLIT)     // 512
#define NSTAGE  (KPER / 32)            // 16 stages of 32 k
#define NSTEPG  (K_TOTAL / 16)         // 256 global k-steps
#define WARPS_CTA 4
#define THREADS  (WARPS_CTA * 32)
#define MB_ROWS  128
#define NMB      (M_TOTAL / MB_ROWS)   // 64
#define NCTA     (NMB * KSPLIT)        // 512

__device__ float g_part[(size_t)KSPLIT * M_TOTAL * N_OUT];  // 8 MB (L2-hot)
__device__ uint4 g_whi2[NSTEPG * 4 * 2 * 8];                // 256 KB
__device__ uint4 g_wlo2[NSTEPG * 4 * 2 * 8];                // 256 KB
__device__ int   g_cnt[NMB];

__device__ __forceinline__ void split2(float f0, float f1,
                                       uint32_t& hp, uint32_t& lp) {
    asm("cvt.rn.bf16x2.f32 %0, %1, %2;" : "=r"(hp) : "f"(f1), "f"(f0));
    float h0 = __uint_as_float(hp << 16);
    float h1 = __uint_as_float(hp & 0xffff0000u);
    float g0 = f0 - h0, g1 = f1 - h1;
    asm("cvt.rn.bf16x2.f32 %0, %1, %2;" : "=r"(lp) : "f"(g1), "f"(g0));
}

__device__ __forceinline__ void mma16816(float* d, const uint32_t* a,
                                         uint32_t b0, uint32_t b1) {
    asm volatile(
        "mma.sync.aligned.m16n8k16.row.col.f32.bf16.bf16.f32 "
        "{%0,%1,%2,%3}, {%4,%5,%6,%7}, {%8,%9}, {%0,%1,%2,%3};"
        : "+f"(d[0]), "+f"(d[1]), "+f"(d[2]), "+f"(d[3])
        : "r"(a[0]), "r"(a[1]), "r"(a[2]), "r"(a[3]), "r"(b0), "r"(b1));
}

__device__ __forceinline__ uint32_t smem_u32(const void* p) {
    uint32_t a;
    asm("{ .reg .u64 t; cvta.to.shared.u64 t, %1; cvt.u32.u64 %0, t; }"
        : "=r"(a) : "l"(p));
    return a;
}
__device__ __forceinline__ void cp16(uint32_t dst, const void* src) {
    asm volatile("cp.async.cg.shared.global [%0], [%1], 16;"
                 :: "r"(dst), "l"(src) : "memory");
}
__device__ __forceinline__ void cp_commit() {
    asm volatile("cp.async.commit_group;" ::: "memory");
}
template <int N>
__device__ __forceinline__ void cp_wait() {
    asm volatile("cp.async.wait_group %0;" :: "n"(N) : "memory");
}

// ---- W pre-split: idx = ((sg*4 + c)*2 + h)*8 + r  (16B uint4 units)
// word j of entry = bf16x2( W[k][j*8+r], W[k+1][j*8+r] ), k = sg*16+c*4+h*2.
__global__ void __launch_bounds__(128)
wsplit_kernel(const float* __restrict__ w) {
    const int t = blockIdx.x * 128 + threadIdx.x;   // 16384
    const int r = t & 7, h = (t >> 3) & 1, c = (t >> 4) & 3, sg = t >> 6;
    const int k = sg * 16 + c * 4 + h * 2;
    uint32_t hi[4], lo[4];
    #pragma unroll
    for (int j = 0; j < 4; j++) {
        const int n = j * 8 + r;
        split2(w[(size_t)k * N_OUT + n], w[(size_t)(k + 1) * N_OUT + n],
               hi[j], lo[j]);
    }
    g_whi2[t] = make_uint4(hi[0], hi[1], hi[2], hi[3]);
    g_wlo2[t] = make_uint4(lo[0], lo[1], lo[2], lo[3]);
}

__global__ void __launch_bounds__(THREADS)
gemm_hmma_kernel(const float* __restrict__ x, float* __restrict__ out) {
    __shared__ __align__(16) char As[2][128 * 128];   // 2 x 16KB A stages

    const int tid  = threadIdx.x;
    const int wid  = tid >> 5, lane = tid & 31;
    const int mb   = blockIdx.x & (NMB - 1);
    const int kp   = blockIdx.x >> 6;
    const int k0   = kp * KPER;
    const int m0c  = mb * MB_ROWS;
    const int r    = lane >> 2;
    const int c    = lane & 3;

    // cp.async fill pattern: thread handles rows (tid>>3)+16q, chunk tid&7
    const int frow   = tid >> 3;
    const int fchunk = tid & 7;
    const int fp     = fchunk ^ ((frow & 1) << 2);   // parity-swizzled slot
    const float* fsrc = x + (size_t)(m0c + frow) * K_TOTAL + k0 + fchunk * 4;
    const uint32_t asbase[2] = { smem_u32(As[0]), smem_u32(As[1]) };

    auto issue_stage = [&](int s, int buf) {
        const uint32_t dst0 = asbase[buf] + frow * 128 + fp * 16;
        const float*   src0 = fsrc + s * 32;
        #pragma unroll
        for (int q = 0; q < 8; q++)
            cp16(dst0 + q * 16 * 128, src0 + (size_t)(q * 16) * K_TOTAL);
    };

    float d[2][4][4];
    #pragma unroll
    for (int i = 0; i < 2; i++)
        #pragma unroll
        for (int j = 0; j < 4; j++)
            #pragma unroll
            for (int q = 0; q < 4; q++) d[i][j][q] = 0.f;

    issue_stage(0, 0); cp_commit();
    issue_stage(1, 1); cp_commit();

    const size_t bb = (size_t)(kp * (KPER / 16)) * 64 + c * 16 + r;

    #pragma unroll 1
    for (int s = 0; s < NSTAGE; s++) {
        cp_wait<1>();
        __syncthreads();
        const char* bs = As[s & 1];
        #pragma unroll
        for (int st = 0; st < 2; st++) {
            // ---- B fragments: 4 LDG.128, full lines ----
            const size_t u = bb + (size_t)(s * 2 + st) * 64;
            const uint4 h0 = g_whi2[u], h1 = g_whi2[u + 8];
            const uint4 l0 = g_wlo2[u], l1 = g_wlo2[u + 8];
            // ---- A fragments from smem (parity swizzle, conflict-free) ----
            const int p = (st * 4 + c) ^ ((r & 1) << 2);
            uint32_t ahi[2][4], alo[2][4];
            #pragma unroll
            for (int i = 0; i < 2; i++) {
                const int row0 = wid * 32 + i * 16 + r;
                const float4 a0 = *(const float4*)(bs + row0 * 128 + p * 16);
                const float4 a1 = *(const float4*)(bs + (row0 + 8) * 128 + p * 16);
                split2(a0.x, a0.y, ahi[i][0], alo[i][0]);
                split2(a1.x, a1.y, ahi[i][1], alo[i][1]);
                split2(a0.z, a0.w, ahi[i][2], alo[i][2]);
                split2(a1.z, a1.w, ahi[i][3], alo[i][3]);
            }
            const uint32_t* bh0 = &h0.x; const uint32_t* bh1 = &h1.x;
            const uint32_t* bl0 = &l0.x; const uint32_t* bl1 = &l1.x;
            #pragma unroll
            for (int i = 0; i < 2; i++)
                #pragma unroll
                for (int j = 0; j < 4; j++) {
                    mma16816(d[i][j], ahi[i], bh0[j], bh1[j]);
                    mma16816(d[i][j], ahi[i], bl0[j], bl1[j]);
                    mma16816(d[i][j], alo[i], bh0[j], bh1[j]);
                }
        }
        __syncthreads();
        if (s + 2 < NSTAGE) issue_stage(s + 2, s & 1);
        cp_commit();
    }

    // ---- store partials ----
    const int m0 = m0c + wid * 32;
    float* base = g_part + ((size_t)kp * M_TOTAL + m0) * N_OUT;
    #pragma unroll
    for (int i = 0; i < 2; i++)
        #pragma unroll
        for (int j = 0; j < 4; j++) {
            const int col = j * 8 + c * 2;
            *(float2*)(base + (size_t)(i * 16 + r)     * N_OUT + col) =
                make_float2(d[i][j][0], d[i][j][1]);
            *(float2*)(base + (size_t)(i * 16 + r + 8) * N_OUT + col) =
                make_float2(d[i][j][2], d[i][j][3]);
        }

    // ---- deterministic fused reduction (last CTA per m-block) ----
    __shared__ int s_last;
    __threadfence();
    __syncthreads();
    if (tid == 0) {
        s_last = (atomicAdd(&g_cnt[mb], 1) == KSPLIT - 1);
        if (s_last) __threadfence();
    }
    __syncthreads();
    if (s_last) {
        const int nf4 = MB_ROWS * N_OUT / 4;              // 1024 float4
        const float4* sc = (const float4*)g_part;
        float4* dst = (float4*)out + (size_t)mb * nf4;
        #pragma unroll 1
        for (int q = tid; q < nf4; q += THREADS) {
            const size_t o = (size_t)mb * nf4 + q;
            float4 v[KSPLIT];
            #pragma unroll
            for (int p = 0; p < KSPLIT; p++)
                v[p] = sc[(size_t)p * (M_TOTAL * N_OUT / 4) + o];
            float4 sv = v[0];
            #pragma unroll
            for (int p = 1; p < KSPLIT; p++) {
                sv.x += v[p].x; sv.y += v[p].y;
                sv.z += v[p].z; sv.w += v[p].w;
            }
            dst[q] = sv;
        }
        if (tid == 0) g_cnt[mb] = 0;   // reset for graph replay
    }
}

extern "C" void kernel_launch(void* const* d_in, const int* in_sizes, int n_in,
                              void* d_out, int out_size) {
    const float* x = (const float*)d_in[0];   // [8192, 4096]
    const float* w = (const float*)d_in[1];   // [4096, 32]
    float* out = (float*)d_out;               // [8192, 32]

    wsplit_kernel<<<NSTEPG * 4 * 2 * 8 / 128, 128>>>(w);
    gemm_hmma_kernel<<<NCTA, THREADS>>>(x, out);
}